// round 2
// baseline (speedup 1.0000x reference)
#include <cuda_runtime.h>
#include <math.h>

// Problem shape (fixed by dataset): B=8, L=2048, E=8, D=512
#define NTOK   16384            // B*L
#define NE     8
#define ND     512
#define NROWS  (NTOK * NE)      // 131072

// Scratch for neighbor_msg M = strength @ X  (256 MB). __device__ global is
// the sanctioned scratch mechanism (no allocs allowed anywhere).
__device__ float g_M[(size_t)NROWS * ND];

__device__ __forceinline__ float sigmoidf(float z) {
    return 1.0f / (1.0f + __expf(-z));
}

__device__ __forceinline__ float gelu_exact(float z) {
    // jax.nn.gelu(approximate=False): 0.5*z*(1+erf(z/sqrt(2)))
    return 0.5f * z * (1.0f + erff(z * 0.70710678118654752f));
}

// ---------------------------------------------------------------------------
// Kernel 1: per-token prep. One CTA per (b,l) token.
//   a[e] = x[e]·wa, b[e] = x[e]·wb
//   s[i][j] = (i!=j) * sigmoid(adjL[i][j]) * sigmoid(a[i]+b[j]+b_msg)
//   M[i][d] = sum_j s[i][j] * x[j][d]
// ---------------------------------------------------------------------------
__global__ __launch_bounds__(256) void prep_kernel(
    const float* __restrict__ x,       // [NTOK, NE, ND]
    const float* __restrict__ w_msg,   // [2*ND]
    const float* __restrict__ b_msg,   // [1]
    const float* __restrict__ adjL)    // [NE, NE]
{
    __shared__ float sx[NE * ND];     // 16 KB token tile
    __shared__ float swm[2 * ND];     // wa | wb
    __shared__ float sa[NE], sb[NE];
    __shared__ float ss[NE * NE];

    const int tid = threadIdx.x;
    const int token = blockIdx.x;

    const float4* xin = reinterpret_cast<const float4*>(x + (size_t)token * (NE * ND));
    float4* sx4 = reinterpret_cast<float4*>(sx);
    #pragma unroll 4
    for (int i = tid; i < NE * ND / 4; i += 256) sx4[i] = xin[i];

    const float4* wm4 = reinterpret_cast<const float4*>(w_msg);
    float4* swm4 = reinterpret_cast<float4*>(swm);
    for (int i = tid; i < 2 * ND / 4; i += 256) swm4[i] = wm4[i];
    __syncthreads();

    // 8 warps: warp e reduces the two dots for expert e
    {
        const int warp = tid >> 5, lane = tid & 31;
        float pa = 0.f, pb = 0.f;
        #pragma unroll
        for (int d = lane; d < ND; d += 32) {
            float xv = sx[warp * ND + d];
            pa += xv * swm[d];
            pb += xv * swm[ND + d];
        }
        #pragma unroll
        for (int off = 16; off; off >>= 1) {
            pa += __shfl_xor_sync(0xffffffff, pa, off);
            pb += __shfl_xor_sync(0xffffffff, pb, off);
        }
        if (lane == 0) { sa[warp] = pa; sb[warp] = pb; }
    }
    __syncthreads();

    if (tid < NE * NE) {
        const int i = tid >> 3, j = tid & 7;
        float v = 0.f;
        if (i != j)
            v = sigmoidf(adjL[tid]) * sigmoidf(sa[i] + sb[j] + b_msg[0]);
        ss[tid] = v;
    }
    __syncthreads();

    float4* mout = reinterpret_cast<float4*>(g_M + (size_t)token * (NE * ND));
    #pragma unroll 2
    for (int q = tid; q < NE * ND / 4; q += 256) {
        const int i = q >> 7;       // output expert row (ND/4 = 128 float4/row)
        float4 acc = make_float4(0.f, 0.f, 0.f, 0.f);
        #pragma unroll
        for (int j = 0; j < NE; j++) {
            const float s = ss[i * NE + j];
            const float4 xv = sx4[j * (ND / 4) + (q & 127)];
            acc.x += s * xv.x; acc.y += s * xv.y;
            acc.z += s * xv.z; acc.w += s * xv.w;
        }
        mout[q] = acc;
    }
}

// ---------------------------------------------------------------------------
// Kernel 2: out = gelu(M @ Wn^T + X @ Ws^T + bn + bs)
// Single logical GEMM [NROWS x 1024] @ [1024 x 512]; the K range is covered
// by two explicit segment loops (no per-iteration pointer select).
// SIMT tile: BM=BN=64, BK=16, 256 threads, 4x4 microtile per thread.
// ---------------------------------------------------------------------------
#define BM 64
#define BN 64
#define BK 16

struct GemmCtx {
    int tid, rowBase, colBase, tx, ty, lrow, lcol4;
};

__device__ __forceinline__ void gemm_segment(
    const float* __restrict__ A, const float* __restrict__ B,
    const GemmCtx& c, float (&acc)[4][4],
    float (*As)[BM], float (*Bs)[BN])
{
    #pragma unroll 1
    for (int kt = 0; kt < ND / BK; kt++) {
        const int k0 = kt * BK;
        const float4 av = *reinterpret_cast<const float4*>(
            A + (size_t)(c.rowBase + c.lrow) * ND + k0 + c.lcol4);
        const float4 bv = *reinterpret_cast<const float4*>(
            B + (size_t)(c.colBase + c.lrow) * ND + k0 + c.lcol4);

        __syncthreads();
        As[c.lcol4 + 0][c.lrow] = av.x; As[c.lcol4 + 1][c.lrow] = av.y;
        As[c.lcol4 + 2][c.lrow] = av.z; As[c.lcol4 + 3][c.lrow] = av.w;
        Bs[c.lcol4 + 0][c.lrow] = bv.x; Bs[c.lcol4 + 1][c.lrow] = bv.y;
        Bs[c.lcol4 + 2][c.lrow] = bv.z; Bs[c.lcol4 + 3][c.lrow] = bv.w;
        __syncthreads();

        #pragma unroll
        for (int kk = 0; kk < BK; kk++) {
            const float4 a4 = *reinterpret_cast<const float4*>(&As[kk][c.ty * 4]);
            const float4 b4 = *reinterpret_cast<const float4*>(&Bs[kk][c.tx * 4]);
            acc[0][0] += a4.x * b4.x; acc[0][1] += a4.x * b4.y;
            acc[0][2] += a4.x * b4.z; acc[0][3] += a4.x * b4.w;
            acc[1][0] += a4.y * b4.x; acc[1][1] += a4.y * b4.y;
            acc[1][2] += a4.y * b4.z; acc[1][3] += a4.y * b4.w;
            acc[2][0] += a4.z * b4.x; acc[2][1] += a4.z * b4.y;
            acc[2][2] += a4.z * b4.z; acc[2][3] += a4.z * b4.w;
            acc[3][0] += a4.w * b4.x; acc[3][1] += a4.w * b4.y;
            acc[3][2] += a4.w * b4.z; acc[3][3] += a4.w * b4.w;
        }
    }
}

__global__ __launch_bounds__(256) void gemm_kernel(
    const float* __restrict__ x,    // [NROWS, ND]
    const float* __restrict__ Wn,   // [ND, ND] (row = o, col = d)
    const float* __restrict__ bn,   // [ND]
    const float* __restrict__ Ws,   // [ND, ND]
    const float* __restrict__ bs,   // [ND]
    float* __restrict__ out)        // [NROWS, ND]
{
    __shared__ float As[BK][BM];
    __shared__ float Bs[BK][BN];

    GemmCtx c;
    c.tid = threadIdx.x;
    c.rowBase = blockIdx.x * BM;
    c.colBase = blockIdx.y * BN;
    c.tx = c.tid & 15;
    c.ty = c.tid >> 4;
    c.lrow = c.tid >> 2;
    c.lcol4 = (c.tid & 3) * 4;

    float acc[4][4] = {};
    gemm_segment(g_M, Wn, c, acc, As, Bs);   // neighbor path
    gemm_segment(x,   Ws, c, acc, As, Bs);   // self path

    // epilogue: bias + exact gelu, float4 stores
    const int c0 = c.colBase + c.tx * 4;
    const float4 bnv = *reinterpret_cast<const float4*>(bn + c0);
    const float4 bsv = *reinterpret_cast<const float4*>(bs + c0);
    const float4 bias = make_float4(bnv.x + bsv.x, bnv.y + bsv.y,
                                    bnv.z + bsv.z, bnv.w + bsv.w);
    #pragma unroll
    for (int m = 0; m < 4; m++) {
        const int row = c.rowBase + c.ty * 4 + m;
        float4 o;
        o.x = gelu_exact(acc[m][0] + bias.x);
        o.y = gelu_exact(acc[m][1] + bias.y);
        o.z = gelu_exact(acc[m][2] + bias.z);
        o.w = gelu_exact(acc[m][3] + bias.w);
        *reinterpret_cast<float4*>(out + (size_t)row * ND + c0) = o;
    }
}

// ---------------------------------------------------------------------------
// Launch. Input order (metadata): expert_features, W_neighbor, b_neighbor,
// W_self, b_self, w_msg, b_msg, adjacency_logits. Output fp32 [B,L,E,D].
// ---------------------------------------------------------------------------
extern "C" void kernel_launch(void* const* d_in, const int* in_sizes, int n_in,
                              void* d_out, int out_size)
{
    const float* x     = (const float*)d_in[0];
    const float* Wn    = (const float*)d_in[1];
    const float* bn    = (const float*)d_in[2];
    const float* Ws    = (const float*)d_in[3];
    const float* bs    = (const float*)d_in[4];
    const float* w_msg = (const float*)d_in[5];
    const float* b_msg = (const float*)d_in[6];
    const float* adjL  = (const float*)d_in[7];
    float* out = (float*)d_out;

    prep_kernel<<<NTOK, 256>>>(x, w_msg, b_msg, adjL);

    dim3 grid(NROWS / BM, ND / BN);   // 2048 x 8
    gemm_kernel<<<grid, 256>>>(x, Wn, bn, Ws, bs, out);
}

// round 6
// speedup vs baseline: 2.9522x; 2.9522x over previous
#include <cuda_runtime.h>
#include <cuda_bf16.h>
#include <math.h>
#include <stdint.h>

// Shape (fixed): B=8, L=2048, E=8, D=512
#define NTOK   16384
#define NE     8
#define ND     512
#define NROWS  (NTOK * NE)          // 131072

// ---------------- device scratch (allocs forbidden; __device__ globals OK) --
__device__ __nv_bfloat16 g_Xhi[(size_t)NROWS * ND];   // 128 MB
__device__ __nv_bfloat16 g_Xlo[(size_t)NROWS * ND];   // 128 MB
__device__ __nv_bfloat16 g_Wnhi[ND * ND], g_Wnlo[ND * ND];
__device__ __nv_bfloat16 g_Wshi[ND * ND], g_Wslo[ND * ND];
__device__ float g_S[(size_t)NTOK * NE * NE];         // 4 MB
__device__ float g_bias[ND];

__device__ __forceinline__ float sigmoidf_(float z) { return 1.0f / (1.0f + __expf(-z)); }
__device__ __forceinline__ float gelu_exact(float z) {
    return 0.5f * z * (1.0f + erff(z * 0.70710678118654752f));
}
__device__ __forceinline__ uint32_t smem_u32(const void* p) {
    uint32_t a;
    asm("{ .reg .u64 t; cvta.to.shared.u64 t, %1; cvt.u32.u64 %0, t; }" : "=r"(a) : "l"(p));
    return a;
}
__device__ __forceinline__ void cp16(uint32_t dst, const void* src) {
    asm volatile("cp.async.cg.shared.global [%0], [%1], 16;" :: "r"(dst), "l"(src));
}
__device__ __forceinline__ void ldm_x4(uint32_t* r, uint32_t addr) {
    asm volatile("ldmatrix.sync.aligned.m8n8.x4.shared.b16 {%0,%1,%2,%3}, [%4];"
                 : "=r"(r[0]), "=r"(r[1]), "=r"(r[2]), "=r"(r[3]) : "r"(addr));
}
__device__ __forceinline__ void ldm_x2(uint32_t* r, uint32_t addr) {
    asm volatile("ldmatrix.sync.aligned.m8n8.x2.shared.b16 {%0,%1}, [%2];"
                 : "=r"(r[0]), "=r"(r[1]) : "r"(addr));
}
__device__ __forceinline__ void mma16816(float* c, const uint32_t* a, const uint32_t* b) {
    asm volatile(
        "mma.sync.aligned.m16n8k16.row.col.f32.bf16.bf16.f32 "
        "{%0,%1,%2,%3}, {%4,%5,%6,%7}, {%8,%9}, {%0,%1,%2,%3};"
        : "+f"(c[0]), "+f"(c[1]), "+f"(c[2]), "+f"(c[3])
        : "r"(a[0]), "r"(a[1]), "r"(a[2]), "r"(a[3]), "r"(b[0]), "r"(b[1]));
}

// ---------------------------------------------------------------------------
// Prep 1: per-token strength matrix + X bf16 hi/lo split.
// ---------------------------------------------------------------------------
__global__ __launch_bounds__(256) void prep_token_kernel(
    const float* __restrict__ x, const float* __restrict__ w_msg,
    const float* __restrict__ b_msg, const float* __restrict__ adjL)
{
    __shared__ float sx[NE * ND];
    __shared__ float swm[2 * ND];
    __shared__ float sa[NE], sb[NE];

    const int tid = threadIdx.x;
    const int token = blockIdx.x;

    const float4* xin = reinterpret_cast<const float4*>(x + (size_t)token * (NE * ND));
    float4* sx4 = reinterpret_cast<float4*>(sx);
    #pragma unroll 4
    for (int i = tid; i < NE * ND / 4; i += 256) sx4[i] = xin[i];
    const float4* wm4 = reinterpret_cast<const float4*>(w_msg);
    float4* swm4 = reinterpret_cast<float4*>(swm);
    for (int i = tid; i < 2 * ND / 4; i += 256) swm4[i] = wm4[i];
    __syncthreads();

    {
        const int warp = tid >> 5, lane = tid & 31;
        float pa = 0.f, pb = 0.f;
        #pragma unroll
        for (int d = lane; d < ND; d += 32) {
            float xv = sx[warp * ND + d];
            pa += xv * swm[d];
            pb += xv * swm[ND + d];
        }
        #pragma unroll
        for (int off = 16; off; off >>= 1) {
            pa += __shfl_xor_sync(0xffffffff, pa, off);
            pb += __shfl_xor_sync(0xffffffff, pb, off);
        }
        if (lane == 0) { sa[warp] = pa; sb[warp] = pb; }
    }
    __syncthreads();

    if (tid < NE * NE) {
        const int i = tid >> 3, j = tid & 7;
        float v = 0.f;
        if (i != j)
            v = sigmoidf_(adjL[tid]) * sigmoidf_(sa[i] + sb[j] + b_msg[0]);
        g_S[(size_t)token * 64 + tid] = v;
    }

    const size_t base = (size_t)token * (NE * ND);
    #pragma unroll 4
    for (int i = tid; i < NE * ND / 4; i += 256) {
        float4 v = sx4[i];
        __nv_bfloat162 h0 = __floats2bfloat162_rn(v.x, v.y);
        __nv_bfloat162 h1 = __floats2bfloat162_rn(v.z, v.w);
        float lx = v.x - __low2float(h0),  ly = v.y - __high2float(h0);
        float lz = v.z - __low2float(h1),  lw = v.w - __high2float(h1);
        __nv_bfloat162 l0 = __floats2bfloat162_rn(lx, ly);
        __nv_bfloat162 l1 = __floats2bfloat162_rn(lz, lw);
        uint2 uh, ul;
        uh.x = *reinterpret_cast<uint32_t*>(&h0); uh.y = *reinterpret_cast<uint32_t*>(&h1);
        ul.x = *reinterpret_cast<uint32_t*>(&l0); ul.y = *reinterpret_cast<uint32_t*>(&l1);
        *reinterpret_cast<uint2*>(g_Xhi + base + (size_t)i * 4) = uh;
        *reinterpret_cast<uint2*>(g_Xlo + base + (size_t)i * 4) = ul;
    }
}

__global__ __launch_bounds__(256) void prep_weight_kernel(
    const float* __restrict__ Wn, const float* __restrict__ bn,
    const float* __restrict__ Ws, const float* __restrict__ bs)
{
    const int idx = blockIdx.x * 256 + threadIdx.x;
    if (idx < ND * ND) {
        float wn = Wn[idx];
        __nv_bfloat16 h = __float2bfloat16(wn);
        g_Wnhi[idx] = h;
        g_Wnlo[idx] = __float2bfloat16(wn - __bfloat162float(h));
        float ws = Ws[idx];
        __nv_bfloat16 h2 = __float2bfloat16(ws);
        g_Wshi[idx] = h2;
        g_Wslo[idx] = __float2bfloat16(ws - __bfloat162float(h2));
    }
    if (idx < ND) g_bias[idx] = bn[idx] + bs[idx];
}

// ---------------------------------------------------------------------------
// HMMA GEMM: per CTA rows 128 (16 tokens x 8 experts), cols 64, K=512.
// P = X@Wn^T and S = X@Ws^T accumulated together (3-pass bf16 split each).
// Epilogue: out = gelu( per-token 8x8 mix of P + S + bias ).
// ---------------------------------------------------------------------------
#define BKC      32                      // k per chunk
#define NCHUNKS  (ND / BKC)              // 16
#define APAD     40                      // row stride in bf16 elems (80 B)
#define A_BYTES  (128 * APAD * 2)        // 10240
#define W_BYTES  (64 * APAD * 2)         // 5120
#define STG_B    (2 * A_BYTES + 4 * W_BYTES)   // 40960
#define SM_STAGE 4352                    // after sbias(256) + ssmat(4096)
#define SMEM_TOTAL (SM_STAGE + 2 * STG_B)      // 86272
#define EPS_STRIDE 66

__global__ __launch_bounds__(256) void gemm_hmma_kernel(float* __restrict__ out)
{
    extern __shared__ char sm[];
    const int tid = threadIdx.x;
    const int wid = tid >> 5, lane = tid & 31;
    const int warpM = wid & 3, warpN = wid >> 2;      // 4 x 2 warp grid

    const int ntile = blockIdx.x;        // 0..7  (fast: siblings share A rows in L2)
    const int mtile = blockIdx.y;        // 0..1023
    const int colBase = ntile * 64;
    const int rowBase = mtile * 128;
    const int tokBase = mtile * 16;

    float* sbias = reinterpret_cast<float*>(sm);
    float* ssmat = reinterpret_cast<float*>(sm + 256);
    if (tid < 64) sbias[tid] = g_bias[colBase + tid];
    for (int i = tid; i < 1024; i += 256) ssmat[i] = g_S[(size_t)tokBase * 64 + i];

    const uint32_t stage0 = smem_u32(sm) + SM_STAGE;
    const __nv_bfloat16* Ahi = g_Xhi + (size_t)rowBase * ND;
    const __nv_bfloat16* Alo = g_Xlo + (size_t)rowBase * ND;
    const __nv_bfloat16* Bnh = g_Wnhi + (size_t)colBase * ND;
    const __nv_bfloat16* Bnl = g_Wnlo + (size_t)colBase * ND;
    const __nv_bfloat16* Bsh = g_Wshi + (size_t)colBase * ND;
    const __nv_bfloat16* Bsl = g_Wslo + (size_t)colBase * ND;

    // ---- async chunk loader: 8 x 16B per thread per chunk ----
    auto issue_chunk = [&](int c) {
        const uint32_t sb = stage0 + (c & 1) * STG_B;
        const int koff = c * BKC;
        #pragma unroll
        for (int i = 0; i < 2; i++) {                 // A hi/lo: 512 copies each
            const int q = tid + i * 256;
            const int row = q >> 2, seg = q & 3;
            const uint32_t d = (row * APAD + seg * 8) * 2;
            cp16(sb + d,           Ahi + (size_t)row * ND + koff + seg * 8);
            cp16(sb + A_BYTES + d, Alo + (size_t)row * ND + koff + seg * 8);
        }
        {                                             // W tiles: 256 copies each
            const int row = tid >> 2, seg = tid & 3;
            const uint32_t d = (row * APAD + seg * 8) * 2;
            const size_t g = (size_t)row * ND + koff + seg * 8;
            cp16(sb + 2 * A_BYTES + 0 * W_BYTES + d, Bnh + g);
            cp16(sb + 2 * A_BYTES + 1 * W_BYTES + d, Bnl + g);
            cp16(sb + 2 * A_BYTES + 2 * W_BYTES + d, Bsh + g);
            cp16(sb + 2 * A_BYTES + 3 * W_BYTES + d, Bsl + g);
        }
    };

    float accP[2][4][4], accS[2][4][4];
    #pragma unroll
    for (int mt = 0; mt < 2; mt++)
        #pragma unroll
        for (int nt = 0; nt < 4; nt++)
            #pragma unroll
            for (int u = 0; u < 4; u++) { accP[mt][nt][u] = 0.f; accS[mt][nt][u] = 0.f; }

    issue_chunk(0);
    asm volatile("cp.async.commit_group;" ::: "memory");

    // ldmatrix lane address components
    const int a_row = ((lane >> 3) & 1) * 8 + (lane & 7);
    const int a_col = (lane >> 4) * 8;
    const int b_row = lane & 7;
    const int b_half = (lane >> 3) & 1;

    #pragma unroll 1
    for (int c = 0; c < NCHUNKS; c++) {
        if (c + 1 < NCHUNKS) {
            issue_chunk(c + 1);
            asm volatile("cp.async.commit_group;" ::: "memory");
            asm volatile("cp.async.wait_group 1;" ::: "memory");
        } else {
            asm volatile("cp.async.wait_group 0;" ::: "memory");
        }
        __syncthreads();

        const uint32_t sb = stage0 + (c & 1) * STG_B;
        #pragma unroll
        for (int ks = 0; ks < 2; ks++) {
            const int k0 = ks * 16;
            uint32_t ahi[2][4], alo[2][4];
            #pragma unroll
            for (int mt = 0; mt < 2; mt++) {
                const uint32_t ra = sb +
                    ((warpM * 32 + mt * 16 + a_row) * APAD + k0 + a_col) * 2;
                ldm_x4(ahi[mt], ra);
                ldm_x4(alo[mt], ra + A_BYTES);
            }
            #pragma unroll
            for (int nt = 0; nt < 4; nt++) {
                const uint32_t bo = sb + 2 * A_BYTES +
                    ((warpN * 32 + nt * 8 + b_row) * APAD + k0 + b_half * 8) * 2;
                uint32_t bnh[2], bnl[2], bsh[2], bsl[2];
                ldm_x2(bnh, bo);
                ldm_x2(bnl, bo + W_BYTES);
                ldm_x2(bsh, bo + 2 * W_BYTES);
                ldm_x2(bsl, bo + 3 * W_BYTES);
                #pragma unroll
                for (int mt = 0; mt < 2; mt++) {
                    mma16816(accP[mt][nt], ahi[mt], bnh);   // hi*hi
                    mma16816(accP[mt][nt], ahi[mt], bnl);   // hi*lo
                    mma16816(accP[mt][nt], alo[mt], bnh);   // lo*hi
                    mma16816(accS[mt][nt], ahi[mt], bsh);
                    mma16816(accS[mt][nt], ahi[mt], bsl);
                    mma16816(accS[mt][nt], alo[mt], bsh);
                }
            }
        }
        __syncthreads();   // all compute done before next chunk overwrites buffer
    }

    // ---- epilogue: acc -> smem (P, S full tiles), then mix + gelu + store --
    float* sP = reinterpret_cast<float*>(sm + SM_STAGE);
    float* sS = sP + 128 * EPS_STRIDE;
    {
        const int rr = lane >> 2;
        const int cc = 2 * (lane & 3);
        #pragma unroll
        for (int mt = 0; mt < 2; mt++) {
            #pragma unroll
            for (int nt = 0; nt < 4; nt++) {
                const int r0 = warpM * 32 + mt * 16 + rr;
                const int c0 = warpN * 32 + nt * 8 + cc;
                sP[r0 * EPS_STRIDE + c0]       = accP[mt][nt][0];
                sP[r0 * EPS_STRIDE + c0 + 1]   = accP[mt][nt][1];
                sP[(r0 + 8) * EPS_STRIDE + c0]     = accP[mt][nt][2];
                sP[(r0 + 8) * EPS_STRIDE + c0 + 1] = accP[mt][nt][3];
                sS[r0 * EPS_STRIDE + c0]       = accS[mt][nt][0];
                sS[r0 * EPS_STRIDE + c0 + 1]   = accS[mt][nt][1];
                sS[(r0 + 8) * EPS_STRIDE + c0]     = accS[mt][nt][2];
                sS[(r0 + 8) * EPS_STRIDE + c0 + 1] = accS[mt][nt][3];
            }
        }
    }
    __syncthreads();

    {
        const int r = tid >> 1;              // local row 0..127
        const int cg = (tid & 1) * 32;       // col half
        const int tt = r >> 3, ei = r & 7;
        float sreg[8];
        #pragma unroll
        for (int j = 0; j < 8; j++) sreg[j] = ssmat[tt * 64 + ei * 8 + j];

        float* outrow = out + (size_t)(rowBase + r) * ND + colBase + cg;
        #pragma unroll
        for (int q = 0; q < 8; q++) {        // 8 x float4
            float4 o;
            #pragma unroll
            for (int u = 0; u < 4; u++) {
                const int cc = cg + q * 4 + u;
                float mix = 0.f;
                #pragma unroll
                for (int j = 0; j < 8; j++)
                    mix = fmaf(sreg[j], sP[(tt * 8 + j) * EPS_STRIDE + cc], mix);
                const float val = mix + sS[r * EPS_STRIDE + cc] + sbias[cc];
                (&o.x)[u] = gelu_exact(val);
            }
            *reinterpret_cast<float4*>(outrow + q * 4) = o;
        }
    }
}

// ---------------------------------------------------------------------------
extern "C" void kernel_launch(void* const* d_in, const int* in_sizes, int n_in,
                              void* d_out, int out_size)
{
    const float* x     = (const float*)d_in[0];
    const float* Wn    = (const float*)d_in[1];
    const float* bn    = (const float*)d_in[2];
    const float* Ws    = (const float*)d_in[3];
    const float* bs    = (const float*)d_in[4];
    const float* w_msg = (const float*)d_in[5];
    const float* b_msg = (const float*)d_in[6];
    const float* adjL  = (const float*)d_in[7];
    float* out = (float*)d_out;

    static bool attr_done = false;
    if (!attr_done) {
        cudaFuncSetAttribute(gemm_hmma_kernel,
                             cudaFuncAttributeMaxDynamicSharedMemorySize, SMEM_TOTAL);
        attr_done = true;
    }

    prep_token_kernel<<<NTOK, 256>>>(x, w_msg, b_msg, adjL);
    prep_weight_kernel<<<(ND * ND + 255) / 256, 256>>>(Wn, bn, Ws, bs);

    dim3 grid(ND / 64, NROWS / 128);     // (8, 1024)
    gemm_hmma_kernel<<<grid, 256, SMEM_TOTAL>>>(out);
}

// round 9
// speedup vs baseline: 3.0464x; 1.0319x over previous
#include <cuda_runtime.h>
#include <cuda_bf16.h>
#include <math.h>
#include <stdint.h>

// Shape (fixed): B=8, L=2048, E=8, D=512
#define NTOK   16384
#define NE     8
#define ND     512
#define NROWS  (NTOK * NE)          // 131072

// ---------------- device scratch (allocs forbidden; __device__ globals OK) --
__device__ __nv_bfloat16 g_Xhi[(size_t)NROWS * ND];   // 128 MB
__device__ __nv_bfloat16 g_Xlo[(size_t)NROWS * ND];   // 128 MB
__device__ __nv_bfloat16 g_Wnhi[ND * ND], g_Wnlo[ND * ND];
__device__ __nv_bfloat16 g_Wshi[ND * ND], g_Wslo[ND * ND];
__device__ float g_S[(size_t)NTOK * NE * NE];         // 4 MB
__device__ float g_bias[ND];

__device__ __forceinline__ float sigmoidf_(float z) { return 1.0f / (1.0f + __expf(-z)); }
__device__ __forceinline__ float gelu_exact(float z) {
    return 0.5f * z * (1.0f + erff(z * 0.70710678118654752f));
}
__device__ __forceinline__ uint32_t smem_u32(const void* p) {
    uint32_t a;
    asm("{ .reg .u64 t; cvta.to.shared.u64 t, %1; cvt.u32.u64 %0, t; }" : "=r"(a) : "l"(p));
    return a;
}
__device__ __forceinline__ void cp16(uint32_t dst, const void* src) {
    asm volatile("cp.async.cg.shared.global [%0], [%1], 16;" :: "r"(dst), "l"(src));
}
__device__ __forceinline__ void ldm_x4(uint32_t* r, uint32_t addr) {
    asm volatile("ldmatrix.sync.aligned.m8n8.x4.shared.b16 {%0,%1,%2,%3}, [%4];"
                 : "=r"(r[0]), "=r"(r[1]), "=r"(r[2]), "=r"(r[3]) : "r"(addr));
}
__device__ __forceinline__ void ldm_x2(uint32_t* r, uint32_t addr) {
    asm volatile("ldmatrix.sync.aligned.m8n8.x2.shared.b16 {%0,%1}, [%2];"
                 : "=r"(r[0]), "=r"(r[1]) : "r"(addr));
}
__device__ __forceinline__ void mma16816(float* c, const uint32_t* a, const uint32_t* b) {
    asm volatile(
        "mma.sync.aligned.m16n8k16.row.col.f32.bf16.bf16.f32 "
        "{%0,%1,%2,%3}, {%4,%5,%6,%7}, {%8,%9}, {%0,%1,%2,%3};"
        : "+f"(c[0]), "+f"(c[1]), "+f"(c[2]), "+f"(c[3])
        : "r"(a[0]), "r"(a[1]), "r"(a[2]), "r"(a[3]), "r"(b[0]), "r"(b[1]));
}

// ---------------------------------------------------------------------------
// Prep 1: per-token strength matrix + X bf16 hi/lo split.  (at DRAM roofline)
// ---------------------------------------------------------------------------
__global__ __launch_bounds__(256) void prep_token_kernel(
    const float* __restrict__ x, const float* __restrict__ w_msg,
    const float* __restrict__ b_msg, const float* __restrict__ adjL)
{
    __shared__ float sx[NE * ND];
    __shared__ float swm[2 * ND];
    __shared__ float sa[NE], sb[NE];

    const int tid = threadIdx.x;
    const int token = blockIdx.x;

    const float4* xin = reinterpret_cast<const float4*>(x + (size_t)token * (NE * ND));
    float4* sx4 = reinterpret_cast<float4*>(sx);
    #pragma unroll 4
    for (int i = tid; i < NE * ND / 4; i += 256) sx4[i] = xin[i];
    const float4* wm4 = reinterpret_cast<const float4*>(w_msg);
    float4* swm4 = reinterpret_cast<float4*>(swm);
    for (int i = tid; i < 2 * ND / 4; i += 256) swm4[i] = wm4[i];
    __syncthreads();

    {
        const int warp = tid >> 5, lane = tid & 31;
        float pa = 0.f, pb = 0.f;
        #pragma unroll
        for (int d = lane; d < ND; d += 32) {
            float xv = sx[warp * ND + d];
            pa += xv * swm[d];
            pb += xv * swm[ND + d];
        }
        #pragma unroll
        for (int off = 16; off; off >>= 1) {
            pa += __shfl_xor_sync(0xffffffff, pa, off);
            pb += __shfl_xor_sync(0xffffffff, pb, off);
        }
        if (lane == 0) { sa[warp] = pa; sb[warp] = pb; }
    }
    __syncthreads();

    if (tid < NE * NE) {
        const int i = tid >> 3, j = tid & 7;
        float v = 0.f;
        if (i != j)
            v = sigmoidf_(adjL[tid]) * sigmoidf_(sa[i] + sb[j] + b_msg[0]);
        g_S[(size_t)token * 64 + tid] = v;
    }

    const size_t base = (size_t)token * (NE * ND);
    #pragma unroll 4
    for (int i = tid; i < NE * ND / 4; i += 256) {
        float4 v = sx4[i];
        __nv_bfloat162 h0 = __floats2bfloat162_rn(v.x, v.y);
        __nv_bfloat162 h1 = __floats2bfloat162_rn(v.z, v.w);
        float lx = v.x - __low2float(h0),  ly = v.y - __high2float(h0);
        float lz = v.z - __low2float(h1),  lw = v.w - __high2float(h1);
        __nv_bfloat162 l0 = __floats2bfloat162_rn(lx, ly);
        __nv_bfloat162 l1 = __floats2bfloat162_rn(lz, lw);
        uint2 uh, ul;
        uh.x = *reinterpret_cast<uint32_t*>(&h0); uh.y = *reinterpret_cast<uint32_t*>(&h1);
        ul.x = *reinterpret_cast<uint32_t*>(&l0); ul.y = *reinterpret_cast<uint32_t*>(&l1);
        *reinterpret_cast<uint2*>(g_Xhi + base + (size_t)i * 4) = uh;
        *reinterpret_cast<uint2*>(g_Xlo + base + (size_t)i * 4) = ul;
    }
}

__global__ __launch_bounds__(256) void prep_weight_kernel(
    const float* __restrict__ Wn, const float* __restrict__ bn,
    const float* __restrict__ Ws, const float* __restrict__ bs)
{
    const int idx = blockIdx.x * 256 + threadIdx.x;
    if (idx < ND * ND) {
        float wn = Wn[idx];
        __nv_bfloat16 h = __float2bfloat16(wn);
        g_Wnhi[idx] = h;
        g_Wnlo[idx] = __float2bfloat16(wn - __bfloat162float(h));
        float ws = Ws[idx];
        __nv_bfloat16 h2 = __float2bfloat16(ws);
        g_Wshi[idx] = h2;
        g_Wslo[idx] = __float2bfloat16(ws - __bfloat162float(h2));
    }
    if (idx < ND) g_bias[idx] = bn[idx] + bs[idx];
}

// ---------------------------------------------------------------------------
// HMMA GEMM: per CTA rows 128 (16 tokens x 8 experts), cols 64, K=512.
// P = X@Wn^T and S = X@Ws^T accumulated together (3-pass bf16 split each).
// Epilogue: out = gelu( per-token 8x8 mix of P + S + bias ).
// R9 (retry of R7/R8): force 2 CTAs/SM (regs <= 128) -> 4 warps/SMSP.
// ---------------------------------------------------------------------------
#define BKC      32                      // k per chunk
#define NCHUNKS  (ND / BKC)              // 16
#define APAD     40                      // row stride in bf16 elems (80 B)
#define A_BYTES  (128 * APAD * 2)        // 10240
#define W_BYTES  (64 * APAD * 2)         // 5120
#define STG_B    (2 * A_BYTES + 4 * W_BYTES)   // 40960
#define SM_STAGE 4352                    // after sbias(256) + ssmat(4096)
#define SMEM_TOTAL (SM_STAGE + 2 * STG_B)      // 86272  (x2 CTAs = 172.5 KB < 227)
#define EPS_STRIDE 66

__global__ __launch_bounds__(256, 2) void gemm_hmma_kernel(float* __restrict__ out)
{
    extern __shared__ char sm[];
    const int tid = threadIdx.x;
    const int wid = tid >> 5, lane = tid & 31;
    const int warpM = wid & 3, warpN = wid >> 2;      // 4 x 2 warp grid

    const int ntile = blockIdx.x;        // 0..7  (fast: siblings share A rows in L2)
    const int mtile = blockIdx.y;        // 0..1023
    const int colBase = ntile * 64;
    const int rowBase = mtile * 128;
    const int tokBase = mtile * 16;

    float* sbias = reinterpret_cast<float*>(sm);
    float* ssmat = reinterpret_cast<float*>(sm + 256);
    if (tid < 64) sbias[tid] = g_bias[colBase + tid];
    for (int i = tid; i < 1024; i += 256) ssmat[i] = g_S[(size_t)tokBase * 64 + i];

    const uint32_t stage0 = smem_u32(sm) + SM_STAGE;
    const __nv_bfloat16* Ahi = g_Xhi + (size_t)rowBase * ND;
    const __nv_bfloat16* Alo = g_Xlo + (size_t)rowBase * ND;
    const __nv_bfloat16* Bnh = g_Wnhi + (size_t)colBase * ND;
    const __nv_bfloat16* Bnl = g_Wnlo + (size_t)colBase * ND;
    const __nv_bfloat16* Bsh = g_Wshi + (size_t)colBase * ND;
    const __nv_bfloat16* Bsl = g_Wslo + (size_t)colBase * ND;

    // ---- async chunk loader: 8 x 16B per thread per chunk ----
    auto issue_chunk = [&](int c) {
        const uint32_t sb = stage0 + (c & 1) * STG_B;
        const int koff = c * BKC;
        #pragma unroll
        for (int i = 0; i < 2; i++) {                 // A hi/lo: 512 copies each
            const int q = tid + i * 256;
            const int row = q >> 2, seg = q & 3;
            const uint32_t d = (row * APAD + seg * 8) * 2;
            cp16(sb + d,           Ahi + (size_t)row * ND + koff + seg * 8);
            cp16(sb + A_BYTES + d, Alo + (size_t)row * ND + koff + seg * 8);
        }
        {                                             // W tiles: 256 copies each
            const int row = tid >> 2, seg = tid & 3;
            const uint32_t d = (row * APAD + seg * 8) * 2;
            const size_t g = (size_t)row * ND + koff + seg * 8;
            cp16(sb + 2 * A_BYTES + 0 * W_BYTES + d, Bnh + g);
            cp16(sb + 2 * A_BYTES + 1 * W_BYTES + d, Bnl + g);
            cp16(sb + 2 * A_BYTES + 2 * W_BYTES + d, Bsh + g);
            cp16(sb + 2 * A_BYTES + 3 * W_BYTES + d, Bsl + g);
        }
    };

    float accP[2][4][4], accS[2][4][4];
    #pragma unroll
    for (int mt = 0; mt < 2; mt++)
        #pragma unroll
        for (int nt = 0; nt < 4; nt++)
            #pragma unroll
            for (int u = 0; u < 4; u++) { accP[mt][nt][u] = 0.f; accS[mt][nt][u] = 0.f; }

    issue_chunk(0);
    asm volatile("cp.async.commit_group;" ::: "memory");

    // ldmatrix lane address components
    const int a_row = ((lane >> 3) & 1) * 8 + (lane & 7);
    const int a_col = (lane >> 4) * 8;
    const int b_row = lane & 7;
    const int b_half = (lane >> 3) & 1;

    #pragma unroll 1
    for (int c = 0; c < NCHUNKS; c++) {
        if (c + 1 < NCHUNKS) {
            issue_chunk(c + 1);
            asm volatile("cp.async.commit_group;" ::: "memory");
            asm volatile("cp.async.wait_group 1;" ::: "memory");
        } else {
            asm volatile("cp.async.wait_group 0;" ::: "memory");
        }
        __syncthreads();

        const uint32_t sb = stage0 + (c & 1) * STG_B;
        #pragma unroll
        for (int ks = 0; ks < 2; ks++) {
            const int k0 = ks * 16;
            uint32_t ahi[2][4], alo[2][4];
            #pragma unroll
            for (int mt = 0; mt < 2; mt++) {
                const uint32_t ra = sb +
                    ((warpM * 32 + mt * 16 + a_row) * APAD + k0 + a_col) * 2;
                ldm_x4(ahi[mt], ra);
                ldm_x4(alo[mt], ra + A_BYTES);
            }
            #pragma unroll
            for (int nt = 0; nt < 4; nt++) {
                const uint32_t bo = sb + 2 * A_BYTES +
                    ((warpN * 32 + nt * 8 + b_row) * APAD + k0 + b_half * 8) * 2;
                uint32_t bnh[2], bnl[2], bsh[2], bsl[2];
                ldm_x2(bnh, bo);
                ldm_x2(bnl, bo + W_BYTES);
                ldm_x2(bsh, bo + 2 * W_BYTES);
                ldm_x2(bsl, bo + 3 * W_BYTES);
                #pragma unroll
                for (int mt = 0; mt < 2; mt++) {
                    mma16816(accP[mt][nt], ahi[mt], bnh);   // hi*hi
                    mma16816(accP[mt][nt], ahi[mt], bnl);   // hi*lo
                    mma16816(accP[mt][nt], alo[mt], bnh);   // lo*hi
                    mma16816(accS[mt][nt], ahi[mt], bsh);
                    mma16816(accS[mt][nt], ahi[mt], bsl);
                    mma16816(accS[mt][nt], alo[mt], bsh);
                }
            }
        }
        __syncthreads();   // all compute done before next chunk overwrites buffer
    }

    // ---- epilogue: acc -> smem (P, S full tiles), then mix + gelu + store --
    float* sP = reinterpret_cast<float*>(sm + SM_STAGE);
    float* sS = sP + 128 * EPS_STRIDE;
    {
        const int rr = lane >> 2;
        const int cc = 2 * (lane & 3);
        #pragma unroll
        for (int mt = 0; mt < 2; mt++) {
            #pragma unroll
            for (int nt = 0; nt < 4; nt++) {
                const int r0 = warpM * 32 + mt * 16 + rr;
                const int c0 = warpN * 32 + nt * 8 + cc;
                sP[r0 * EPS_STRIDE + c0]       = accP[mt][nt][0];
                sP[r0 * EPS_STRIDE + c0 + 1]   = accP[mt][nt][1];
                sP[(r0 + 8) * EPS_STRIDE + c0]     = accP[mt][nt][2];
                sP[(r0 + 8) * EPS_STRIDE + c0 + 1] = accP[mt][nt][3];
                sS[r0 * EPS_STRIDE + c0]       = accS[mt][nt][0];
                sS[r0 * EPS_STRIDE + c0 + 1]   = accS[mt][nt][1];
                sS[(r0 + 8) * EPS_STRIDE + c0]     = accS[mt][nt][2];
                sS[(r0 + 8) * EPS_STRIDE + c0 + 1] = accS[mt][nt][3];
            }
        }
    }
    __syncthreads();

    {
        const int r = tid >> 1;              // local row 0..127
        const int cg = (tid & 1) * 32;       // col half
        const int tt = r >> 3, ei = r & 7;
        float sreg[8];
        #pragma unroll
        for (int j = 0; j < 8; j++) sreg[j] = ssmat[tt * 64 + ei * 8 + j];

        float* outrow = out + (size_t)(rowBase + r) * ND + colBase + cg;
        #pragma unroll
        for (int q = 0; q < 8; q++) {        // 8 x float4
            float4 o;
            #pragma unroll
            for (int u = 0; u < 4; u++) {
                const int cc = cg + q * 4 + u;
                float mix = 0.f;
                #pragma unroll
                for (int j = 0; j < 8; j++)
                    mix = fmaf(sreg[j], sP[(tt * 8 + j) * EPS_STRIDE + cc], mix);
                const float val = mix + sS[r * EPS_STRIDE + cc] + sbias[cc];
                (&o.x)[u] = gelu_exact(val);
            }
            *reinterpret_cast<float4*>(outrow + q * 4) = o;
        }
    }
}

// ---------------------------------------------------------------------------
extern "C" void kernel_launch(void* const* d_in, const int* in_sizes, int n_in,
                              void* d_out, int out_size)
{
    const float* x     = (const float*)d_in[0];
    const float* Wn    = (const float*)d_in[1];
    const float* bn    = (const float*)d_in[2];
    const float* Ws    = (const float*)d_in[3];
    const float* bs    = (const float*)d_in[4];
    const float* w_msg = (const float*)d_in[5];
    const float* b_msg = (const float*)d_in[6];
    const float* adjL  = (const float*)d_in[7];
    float* out = (float*)d_out;

    static bool attr_done = false;
    if (!attr_done) {
        cudaFuncSetAttribute(gemm_hmma_kernel,
                             cudaFuncAttributeMaxDynamicSharedMemorySize, SMEM_TOTAL);
        attr_done = true;
    }

    prep_token_kernel<<<NTOK, 256>>>(x, w_msg, b_msg, adjL);
    prep_weight_kernel<<<(ND * ND + 255) / 256, 256>>>(Wn, bn, Ws, bs);

    dim3 grid(ND / 64, NROWS / 128);     // (8, 1024)
    gemm_hmma_kernel<<<grid, 256, SMEM_TOTAL>>>(out);
}

// round 11
// speedup vs baseline: 6.2085x; 2.0380x over previous
#include <cuda_runtime.h>
#include <cuda_fp16.h>
#include <math.h>
#include <stdint.h>

// Shape (fixed): B=8, L=2048, E=8, D=512
#define NTOK   16384
#define NE     8
#define ND     512
#define NROWS  (NTOK * NE)          // 131072

// ---------------- device scratch (allocs forbidden; __device__ globals OK) --
__device__ __half g_Xh[(size_t)NROWS * ND];    // 128 MB (fp16 X)
__device__ __half g_Wnh[ND * ND];              // fp16 Wn
__device__ __half g_Wsh[ND * ND];              // fp16 Ws
__device__ float  g_S[(size_t)NTOK * NE * NE]; // 4 MB per-token 8x8 strength
__device__ float  g_bias[ND];

__device__ __forceinline__ float sigmoidf_(float z) { return 1.0f / (1.0f + __expf(-z)); }
__device__ __forceinline__ float gelu_exact(float z) {
    return 0.5f * z * (1.0f + erff(z * 0.70710678118654752f));
}
__device__ __forceinline__ uint32_t smem_u32(const void* p) {
    uint32_t a;
    asm("{ .reg .u64 t; cvta.to.shared.u64 t, %1; cvt.u32.u64 %0, t; }" : "=r"(a) : "l"(p));
    return a;
}
__device__ __forceinline__ void cp16(uint32_t dst, const void* src) {
    asm volatile("cp.async.cg.shared.global [%0], [%1], 16;" :: "r"(dst), "l"(src));
}
__device__ __forceinline__ void ldm_x4(uint32_t* r, uint32_t addr) {
    asm volatile("ldmatrix.sync.aligned.m8n8.x4.shared.b16 {%0,%1,%2,%3}, [%4];"
                 : "=r"(r[0]), "=r"(r[1]), "=r"(r[2]), "=r"(r[3]) : "r"(addr));
}
__device__ __forceinline__ void ldm_x2(uint32_t* r, uint32_t addr) {
    asm volatile("ldmatrix.sync.aligned.m8n8.x2.shared.b16 {%0,%1}, [%2];"
                 : "=r"(r[0]), "=r"(r[1]) : "r"(addr));
}
__device__ __forceinline__ void mma16816(float* c, const uint32_t* a, const uint32_t* b) {
    asm volatile(
        "mma.sync.aligned.m16n8k16.row.col.f32.f16.f16.f32 "
        "{%0,%1,%2,%3}, {%4,%5,%6,%7}, {%8,%9}, {%0,%1,%2,%3};"
        : "+f"(c[0]), "+f"(c[1]), "+f"(c[2]), "+f"(c[3])
        : "r"(a[0]), "r"(a[1]), "r"(a[2]), "r"(a[3]), "r"(b[0]), "r"(b[1]));
}

// ---------------------------------------------------------------------------
// Prep 1: per-token strength matrix + X -> fp16.
// ---------------------------------------------------------------------------
__global__ __launch_bounds__(256) void prep_token_kernel(
    const float* __restrict__ x, const float* __restrict__ w_msg,
    const float* __restrict__ b_msg, const float* __restrict__ adjL)
{
    __shared__ float sx[NE * ND];
    __shared__ float swm[2 * ND];
    __shared__ float sa[NE], sb[NE];

    const int tid = threadIdx.x;
    const int token = blockIdx.x;

    const float4* xin = reinterpret_cast<const float4*>(x + (size_t)token * (NE * ND));
    float4* sx4 = reinterpret_cast<float4*>(sx);
    #pragma unroll 4
    for (int i = tid; i < NE * ND / 4; i += 256) sx4[i] = xin[i];
    const float4* wm4 = reinterpret_cast<const float4*>(w_msg);
    float4* swm4 = reinterpret_cast<float4*>(swm);
    for (int i = tid; i < 2 * ND / 4; i += 256) swm4[i] = wm4[i];
    __syncthreads();

    {
        const int warp = tid >> 5, lane = tid & 31;
        float pa = 0.f, pb = 0.f;
        #pragma unroll
        for (int d = lane; d < ND; d += 32) {
            float xv = sx[warp * ND + d];
            pa += xv * swm[d];
            pb += xv * swm[ND + d];
        }
        #pragma unroll
        for (int off = 16; off; off >>= 1) {
            pa += __shfl_xor_sync(0xffffffff, pa, off);
            pb += __shfl_xor_sync(0xffffffff, pb, off);
        }
        if (lane == 0) { sa[warp] = pa; sb[warp] = pb; }
    }
    __syncthreads();

    if (tid < NE * NE) {
        const int i = tid >> 3, j = tid & 7;
        float v = 0.f;
        if (i != j)
            v = sigmoidf_(adjL[tid]) * sigmoidf_(sa[i] + sb[j] + b_msg[0]);
        g_S[(size_t)token * 64 + tid] = v;
    }

    const size_t base = (size_t)token * (NE * ND);
    #pragma unroll 4
    for (int i = tid; i < NE * ND / 4; i += 256) {
        float4 v = sx4[i];
        __half2 h0 = __floats2half2_rn(v.x, v.y);
        __half2 h1 = __floats2half2_rn(v.z, v.w);
        uint2 uh;
        uh.x = *reinterpret_cast<uint32_t*>(&h0);
        uh.y = *reinterpret_cast<uint32_t*>(&h1);
        *reinterpret_cast<uint2*>(g_Xh + base + (size_t)i * 4) = uh;
    }
}

__global__ __launch_bounds__(256) void prep_weight_kernel(
    const float* __restrict__ Wn, const float* __restrict__ bn,
    const float* __restrict__ Ws, const float* __restrict__ bs)
{
    const int idx = blockIdx.x * 256 + threadIdx.x;
    if (idx < ND * ND) {
        g_Wnh[idx] = __float2half_rn(Wn[idx]);
        g_Wsh[idx] = __float2half_rn(Ws[idx]);
    }
    if (idx < ND) g_bias[idx] = bn[idx] + bs[idx];
}

// ---------------------------------------------------------------------------
// fp16 HMMA GEMM: per CTA rows 128 (16 tokens x 8 experts), cols 64, K=512.
// P = X@Wn^T and S = X@Ws^T, single fp16 pass each (fp32 accum).
// Epilogue: out = gelu( per-token 8x8 mix of P + S + bias ).
// ---------------------------------------------------------------------------
#define BKC      64                       // k per chunk
#define NCHUNKS  (ND / BKC)               // 8
#define APAD_B   144                      // row stride bytes (64 fp16 = 128B + 16 pad)
#define A_BYTES  (128 * APAD_B)           // 18432
#define W_BYTES  (64 * APAD_B)            // 9216
#define STG_B    (A_BYTES + 2 * W_BYTES)  // 36864
#define SM_STAGE 4352                     // after sbias(256) + ssmat(4096)
#define SMEM_TOTAL (SM_STAGE + 2 * STG_B) // 78080  (x2 CTAs = 156 KB < 227)
#define EPS_STRIDE 66

__global__ __launch_bounds__(256, 2) void gemm_hmma_kernel(float* __restrict__ out)
{
    extern __shared__ char sm[];
    const int tid = threadIdx.x;
    const int wid = tid >> 5, lane = tid & 31;
    const int warpM = wid & 3, warpN = wid >> 2;      // 4 x 2 warp grid

    const int ntile = blockIdx.x;        // 0..7  (fast: siblings share A rows in L2)
    const int mtile = blockIdx.y;        // 0..1023
    const int colBase = ntile * 64;
    const int rowBase = mtile * 128;
    const int tokBase = mtile * 16;

    float* sbias = reinterpret_cast<float*>(sm);
    float* ssmat = reinterpret_cast<float*>(sm + 256);
    if (tid < 64) sbias[tid] = g_bias[colBase + tid];
    for (int i = tid; i < 1024; i += 256) ssmat[i] = g_S[(size_t)tokBase * 64 + i];

    const uint32_t stage0 = smem_u32(sm) + SM_STAGE;
    const __half* Ah = g_Xh  + (size_t)rowBase * ND;
    const __half* Bn = g_Wnh + (size_t)colBase * ND;
    const __half* Bs = g_Wsh + (size_t)colBase * ND;

    // ---- async chunk loader: 8 x 16B per thread per chunk ----
    auto issue_chunk = [&](int c) {
        const uint32_t sb = stage0 + (c & 1) * STG_B;
        const int koff = c * BKC;
        #pragma unroll
        for (int i = 0; i < 4; i++) {                 // A: 1024 cp16
            const int q = tid + i * 256;
            const int row = q >> 3, seg = q & 7;
            cp16(sb + row * APAD_B + seg * 16,
                 Ah + (size_t)row * ND + koff + seg * 8);
        }
        #pragma unroll
        for (int i = 0; i < 2; i++) {                 // Wn, Ws: 512 cp16 each
            const int q = tid + i * 256;
            const int row = q >> 3, seg = q & 7;
            const uint32_t d = row * APAD_B + seg * 16;
            const size_t g = (size_t)row * ND + koff + seg * 8;
            cp16(sb + A_BYTES + d,           Bn + g);
            cp16(sb + A_BYTES + W_BYTES + d, Bs + g);
        }
    };

    float accP[2][4][4], accS[2][4][4];
    #pragma unroll
    for (int mt = 0; mt < 2; mt++)
        #pragma unroll
        for (int nt = 0; nt < 4; nt++)
            #pragma unroll
            for (int u = 0; u < 4; u++) { accP[mt][nt][u] = 0.f; accS[mt][nt][u] = 0.f; }

    issue_chunk(0);
    asm volatile("cp.async.commit_group;" ::: "memory");

    // ldmatrix lane address components
    const int a_row = ((lane >> 3) & 1) * 8 + (lane & 7);
    const int a_col = (lane >> 4) * 8;
    const int b_row = lane & 7;
    const int b_half = (lane >> 3) & 1;

    #pragma unroll 1
    for (int c = 0; c < NCHUNKS; c++) {
        if (c + 1 < NCHUNKS) {
            issue_chunk(c + 1);
            asm volatile("cp.async.commit_group;" ::: "memory");
            asm volatile("cp.async.wait_group 1;" ::: "memory");
        } else {
            asm volatile("cp.async.wait_group 0;" ::: "memory");
        }
        __syncthreads();

        const uint32_t sb = stage0 + (c & 1) * STG_B;
        #pragma unroll
        for (int ks = 0; ks < 4; ks++) {
            const int k0 = ks * 16;
            uint32_t af[2][4];
            #pragma unroll
            for (int mt = 0; mt < 2; mt++) {
                const uint32_t ra = sb +
                    (warpM * 32 + mt * 16 + a_row) * APAD_B + (k0 + a_col) * 2;
                ldm_x4(af[mt], ra);
            }
            #pragma unroll
            for (int nt = 0; nt < 4; nt++) {
                const uint32_t bo = sb + A_BYTES +
                    (warpN * 32 + nt * 8 + b_row) * APAD_B + (k0 + b_half * 8) * 2;
                uint32_t bn[2], bsw[2];
                ldm_x2(bn,  bo);
                ldm_x2(bsw, bo + W_BYTES);
                #pragma unroll
                for (int mt = 0; mt < 2; mt++) {
                    mma16816(accP[mt][nt], af[mt], bn);
                    mma16816(accS[mt][nt], af[mt], bsw);
                }
            }
        }
        __syncthreads();   // compute done before next chunk overwrites this buffer
    }

    // ---- epilogue: acc -> smem (P, S full tiles), then mix + gelu + store --
    float* sP = reinterpret_cast<float*>(sm + SM_STAGE);
    float* sS = sP + 128 * EPS_STRIDE;
    {
        const int rr = lane >> 2;
        const int cc = 2 * (lane & 3);
        #pragma unroll
        for (int mt = 0; mt < 2; mt++) {
            #pragma unroll
            for (int nt = 0; nt < 4; nt++) {
                const int r0 = warpM * 32 + mt * 16 + rr;
                const int c0 = warpN * 32 + nt * 8 + cc;
                sP[r0 * EPS_STRIDE + c0]       = accP[mt][nt][0];
                sP[r0 * EPS_STRIDE + c0 + 1]   = accP[mt][nt][1];
                sP[(r0 + 8) * EPS_STRIDE + c0]     = accP[mt][nt][2];
                sP[(r0 + 8) * EPS_STRIDE + c0 + 1] = accP[mt][nt][3];
                sS[r0 * EPS_STRIDE + c0]       = accS[mt][nt][0];
                sS[r0 * EPS_STRIDE + c0 + 1]   = accS[mt][nt][1];
                sS[(r0 + 8) * EPS_STRIDE + c0]     = accS[mt][nt][2];
                sS[(r0 + 8) * EPS_STRIDE + c0 + 1] = accS[mt][nt][3];
            }
        }
    }
    __syncthreads();

    {
        const int r = tid >> 1;              // local row 0..127
        const int cg = (tid & 1) * 32;       // col half
        const int tt = r >> 3, ei = r & 7;
        float sreg[8];
        #pragma unroll
        for (int j = 0; j < 8; j++) sreg[j] = ssmat[tt * 64 + ei * 8 + j];

        float* outrow = out + (size_t)(rowBase + r) * ND + colBase + cg;
        #pragma unroll
        for (int q = 0; q < 8; q++) {        // 8 x float4
            float4 o;
            #pragma unroll
            for (int u = 0; u < 4; u++) {
                const int cc = cg + q * 4 + u;
                float mix = 0.f;
                #pragma unroll
                for (int j = 0; j < 8; j++)
                    mix = fmaf(sreg[j], sP[(tt * 8 + j) * EPS_STRIDE + cc], mix);
                const float val = mix + sS[r * EPS_STRIDE + cc] + sbias[cc];
                (&o.x)[u] = gelu_exact(val);
            }
            *reinterpret_cast<float4*>(outrow + q * 4) = o;
        }
    }
}

// ---------------------------------------------------------------------------
extern "C" void kernel_launch(void* const* d_in, const int* in_sizes, int n_in,
                              void* d_out, int out_size)
{
    const float* x     = (const float*)d_in[0];
    const float* Wn    = (const float*)d_in[1];
    const float* bn    = (const float*)d_in[2];
    const float* Ws    = (const float*)d_in[3];
    const float* bs    = (const float*)d_in[4];
    const float* w_msg = (const float*)d_in[5];
    const float* b_msg = (const float*)d_in[6];
    const float* adjL  = (const float*)d_in[7];
    float* out = (float*)d_out;

    static bool attr_done = false;
    if (!attr_done) {
        cudaFuncSetAttribute(gemm_hmma_kernel,
                             cudaFuncAttributeMaxDynamicSharedMemorySize, SMEM_TOTAL);
        attr_done = true;
    }

    prep_token_kernel<<<NTOK, 256>>>(x, w_msg, b_msg, adjL);
    prep_weight_kernel<<<(ND * ND + 255) / 256, 256>>>(Wn, bn, Ws, bs);

    dim3 grid(ND / 64, NROWS / 128);     // (8, 1024)
    gemm_hmma_kernel<<<grid, 256, SMEM_TOTAL>>>(out);
}